// round 7
// baseline (speedup 1.0000x reference)
#include <cuda_runtime.h>
#include <cuda_bf16.h>
#include <cstdint>

// Inverted window cross-attention via warp-level bf16 mma.sync.
// R7: 2 warps per window (32 score rows each), 2 windows per 128-thread CTA.
// Halves B/V ldmatrix redundancy vs R6 (4 warps/window).

typedef unsigned long long ull;

constexpr int Bc = 4, Hc = 128, Wc = 128, Cc = 192;
constexpr int Lc = Hc * Wc;
constexpr long long BLC = (long long)Bc * Lc * Cc;

constexpr int PITCH = 72;                 // bf16 per smem row (144B, ldsm conflict-free)
// per-window tile offsets (bytes); each tile 64 x 72 bf16 (cols 0-31 hi, 32-63 lo)
constexpr int SQ2 = 0, SK2 = 9216, SK1 = 18432, SQ1 = 27648, SV = 36864;
constexpr int WSZ = 46080;                // per-window smem block
constexpr int SMEM_TOTAL = 2 * WSZ;       // 92160

__device__ __forceinline__ uint32_t smem_u32(const void* p) {
    uint32_t a;
    asm("{ .reg .u64 t; cvta.to.shared.u64 t, %1; cvt.u32.u64 %0, t; }" : "=r"(a) : "l"(p));
    return a;
}
__device__ __forceinline__ uint32_t pack_bf16(float lo, float hi) {
    uint32_t r; asm("cvt.rn.bf16x2.f32 %0, %1, %2;" : "=r"(r) : "f"(hi), "f"(lo)); return r;
}
__device__ __forceinline__ float bf_lo(uint32_t p) { return __uint_as_float(p << 16); }
__device__ __forceinline__ float bf_hi(uint32_t p) { return __uint_as_float(p & 0xffff0000u); }

__device__ __forceinline__ void split8(const float* x, uint4& h, uint4& l) {
    uint32_t h0 = pack_bf16(x[0], x[1]), h1 = pack_bf16(x[2], x[3]);
    uint32_t h2 = pack_bf16(x[4], x[5]), h3 = pack_bf16(x[6], x[7]);
    h = make_uint4(h0, h1, h2, h3);
    l = make_uint4(pack_bf16(x[0]-bf_lo(h0), x[1]-bf_hi(h0)),
                   pack_bf16(x[2]-bf_lo(h1), x[3]-bf_hi(h1)),
                   pack_bf16(x[4]-bf_lo(h2), x[5]-bf_hi(h2)),
                   pack_bf16(x[6]-bf_lo(h3), x[7]-bf_hi(h3)));
}

__device__ __forceinline__ void ldsm4(uint32_t* r, uint32_t a) {
    asm volatile("ldmatrix.sync.aligned.m8n8.x4.shared.b16 {%0,%1,%2,%3}, [%4];"
                 : "=r"(r[0]), "=r"(r[1]), "=r"(r[2]), "=r"(r[3]) : "r"(a));
}
__device__ __forceinline__ void ldsm4t(uint32_t* r, uint32_t a) {
    asm volatile("ldmatrix.sync.aligned.m8n8.x4.trans.shared.b16 {%0,%1,%2,%3}, [%4];"
                 : "=r"(r[0]), "=r"(r[1]), "=r"(r[2]), "=r"(r[3]) : "r"(a));
}
__device__ __forceinline__ void mma16816(float* d, const uint32_t* a, const uint32_t* b) {
    asm volatile("mma.sync.aligned.m16n8k16.row.col.f32.bf16.bf16.f32 "
                 "{%0,%1,%2,%3}, {%4,%5,%6,%7}, {%8,%9}, {%0,%1,%2,%3};"
                 : "+f"(d[0]), "+f"(d[1]), "+f"(d[2]), "+f"(d[3])
                 : "r"(a[0]), "r"(a[1]), "r"(a[2]), "r"(a[3]), "r"(b[0]), "r"(b[1]));
}

__global__ __launch_bounds__(128, 2)
void inv_attn_mma2(const float* __restrict__ qkv1,
                   const float* __restrict__ qkv2,
                   float* __restrict__ out)
{
    extern __shared__ char sm[];
    const int tid  = threadIdx.x;
    const int lane = tid & 31;
    const int w    = tid >> 5;        // warp 0..3
    const int wloc = w >> 1;          // window within CTA (0/1)
    const int wsub = w & 1;           // warp within window
    const int head = blockIdx.y;

    const int win = blockIdx.x * 2 + wloc;
    const int b = win >> 8, hb = (win >> 4) & 15, wb = win & 15;
    const int row0  = hb * 8 * Wc + wb * 8;
    const int cbase = head * 32;
    char* sW = sm + wloc * WSZ;

    // ---------------- loader: one token per thread, all 32 dims ----------------
    {
        const int t = tid & 63;
        const long long gt = ((long long)b * Lc + row0 + (t >> 3) * Wc + (t & 7)) * Cc + cbase;
        const float* srcs[4] = { qkv2 + gt, qkv2 + BLC + gt, qkv1 + BLC + gt, qkv1 + gt };
        const int dsts[4] = { SQ2, SK2, SK1, SQ1 };
#pragma unroll
        for (int s = 0; s < 4; s++) {
            const float* g = srcs[s];
            char* dbase = sW + dsts[s] + t * (PITCH * 2);
#pragma unroll
            for (int j = 0; j < 4; j++) {
                const int d = 8 * j;
                float x[8]; uint4 h, l;
                *(float4*)(x)     = *(const float4*)(g + d);
                *(float4*)(x + 4) = *(const float4*)(g + d + 4);
                split8(x, h, l);
                *(uint4*)(dbase + d * 2)        = h;
                *(uint4*)(dbase + (32 + d) * 2) = l;
            }
        }
        const float* v1g = qkv1 + 2 * BLC + gt;
        const float* v2g = qkv1 + 3 * BLC + gt;
        char* dv = sW + SV + t * (PITCH * 2);
#pragma unroll
        for (int j = 0; j < 4; j++) {
            const int d = 8 * j;
            float x[8]; uint4 h, l;
            float4 p = *(const float4*)(v1g + d), q = *(const float4*)(v2g + d);
            x[0] = p.x + q.x; x[1] = p.y + q.y; x[2] = p.z + q.z; x[3] = p.w + q.w;
            p = *(const float4*)(v1g + d + 4); q = *(const float4*)(v2g + d + 4);
            x[4] = p.x + q.x; x[5] = p.y + q.y; x[6] = p.z + q.z; x[7] = p.w + q.w;
            split8(x, h, l);
            *(uint4*)(dv + d * 2)        = h;
            *(uint4*)(dv + (32 + d) * 2) = l;
        }
    }
    __syncthreads();

    const uint32_t smw = smem_u32(sm) + wloc * WSZ;
    const int mat = lane >> 3, li = lane & 7;
    const int r0 = wsub * 32;         // this warp's 32 score rows

    // ldmatrix lane-address parts
    const uint32_t bPart = (li * PITCH + ((mat & 1) << 3) + ((mat >> 1) << 5)) * 2;
    const uint32_t vPart = ((li + ((mat & 1) << 3)) * PITCH + ((mat >> 1) << 5)) * 2;

    // ---------------- A fragments (resident): q2/k2 hi+lo, 2 row-tiles x 2 kc -----
    uint32_t aQh[2][2][4], aQl[2][2][4], aKh[2][2][4], aKl[2][2][4];
#pragma unroll
    for (int i = 0; i < 2; i++) {
        const uint32_t aPart =
            ((r0 + 16 * i + li + ((mat & 1) << 3)) * PITCH + ((mat >> 1) << 3)) * 2;
#pragma unroll
        for (int kc = 0; kc < 2; kc++) {
            ldsm4(aQh[i][kc], smw + SQ2 + aPart + (16 * kc) * 2);
            ldsm4(aQl[i][kc], smw + SQ2 + aPart + (32 + 16 * kc) * 2);
            ldsm4(aKh[i][kc], smw + SK2 + aPart + (16 * kc) * 2);
            ldsm4(aKl[i][kc], smw + SK2 + aPart + (32 + 16 * kc) * 2);
        }
    }

    // ---------------- score MMAs: 32 rows x 64 cols, bf16 3-term split -----------
    float sacc[2][8][4] = {};
#pragma unroll
    for (int j = 0; j < 8; j++) {
#pragma unroll
        for (int kc = 0; kc < 2; kc++) {
            uint32_t bk[4], bq[4];
            const uint32_t off = (j * 8 * PITCH + 16 * kc) * 2;
            ldsm4(bk, smw + SK1 + bPart + off);
            ldsm4(bq, smw + SQ1 + bPart + off);
#pragma unroll
            for (int i = 0; i < 2; i++) {
                mma16816(sacc[i][j], aQh[i][kc], bk);
                mma16816(sacc[i][j], aQl[i][kc], bk);
                mma16816(sacc[i][j], aQh[i][kc], bk + 2);
                mma16816(sacc[i][j], aKh[i][kc], bq);
                mma16816(sacc[i][j], aKl[i][kc], bq);
                mma16816(sacc[i][j], aKh[i][kc], bq + 2);
            }
        }
    }

    // ---------------- register softmax (per row-tile halves) ----------------
    const float scale = 0.17677669529663687f;  // 32^-0.5
    float inv0[2], inv1[2];
#pragma unroll
    for (int i = 0; i < 2; i++) {
        float s0 = 0.f, s1 = 0.f;
#pragma unroll
        for (int j = 0; j < 8; j++) {
            sacc[i][j][0] = __expf(2.f - scale * sacc[i][j][0]);
            sacc[i][j][1] = __expf(2.f - scale * sacc[i][j][1]);
            sacc[i][j][2] = __expf(2.f - scale * sacc[i][j][2]);
            sacc[i][j][3] = __expf(2.f - scale * sacc[i][j][3]);
            s0 += sacc[i][j][0] + sacc[i][j][1];
            s1 += sacc[i][j][2] + sacc[i][j][3];
        }
        s0 += __shfl_xor_sync(0xffffffffu, s0, 1);
        s0 += __shfl_xor_sync(0xffffffffu, s0, 2);
        s1 += __shfl_xor_sync(0xffffffffu, s1, 1);
        s1 += __shfl_xor_sync(0xffffffffu, s1, 2);
        inv0[i] = 1.0f / s0;
        inv1[i] = 1.0f / s1;
    }

    // ---------------- D-frag -> A-frag repack with bf16 split ----------------
    uint32_t ehi[2][4][4], elo[2][4][4];
#pragma unroll
    for (int i = 0; i < 2; i++)
#pragma unroll
        for (int kc = 0; kc < 4; kc++) {
            const float* t0 = sacc[i][2 * kc];
            const float* t1 = sacc[i][2 * kc + 1];
            uint32_t h;
            h = pack_bf16(t0[0], t0[1]); ehi[i][kc][0] = h;
            elo[i][kc][0] = pack_bf16(t0[0] - bf_lo(h), t0[1] - bf_hi(h));
            h = pack_bf16(t0[2], t0[3]); ehi[i][kc][1] = h;
            elo[i][kc][1] = pack_bf16(t0[2] - bf_lo(h), t0[3] - bf_hi(h));
            h = pack_bf16(t1[0], t1[1]); ehi[i][kc][2] = h;
            elo[i][kc][2] = pack_bf16(t1[0] - bf_lo(h), t1[1] - bf_hi(h));
            h = pack_bf16(t1[2], t1[3]); ehi[i][kc][3] = h;
            elo[i][kc][3] = pack_bf16(t1[2] - bf_lo(h), t1[3] - bf_hi(h));
        }

    // ---------------- PV MMAs: 32 rows x 32 dims ----------------
    float oacc[2][4][4] = {};
#pragma unroll
    for (int t = 0; t < 4; t++) {
#pragma unroll
        for (int kc = 0; kc < 4; kc++) {
            uint32_t bv[4];
            ldsm4t(bv, smw + SV + vPart + (16 * kc * PITCH + 8 * t) * 2);  // {vh, vl}
#pragma unroll
            for (int i = 0; i < 2; i++) {
                mma16816(oacc[i][t], ehi[i][kc], bv);
                mma16816(oacc[i][t], ehi[i][kc], bv + 2);
                mma16816(oacc[i][t], elo[i][kc], bv);
            }
        }
    }

    // ---------------- output (1/sum folded) ----------------
    {
        const int r  = lane >> 2;
        const int cq = (lane & 3) * 2;
#pragma unroll
        for (int i = 0; i < 2; i++) {
            const int nA = r0 + 16 * i + r, nB = nA + 8;
            const long long gA =
                ((long long)b * Lc + row0 + (nA >> 3) * Wc + (nA & 7)) * Cc + cbase;
            const long long gB =
                ((long long)b * Lc + row0 + (nB >> 3) * Wc + (nB & 7)) * Cc + cbase;
#pragma unroll
            for (int t = 0; t < 4; t++) {
                *(float2*)(out + gA + 8 * t + cq) =
                    make_float2(oacc[i][t][0] * inv0[i], oacc[i][t][1] * inv0[i]);
                *(float2*)(out + gB + 8 * t + cq) =
                    make_float2(oacc[i][t][2] * inv1[i], oacc[i][t][3] * inv1[i]);
            }
        }
    }
}

extern "C" void kernel_launch(void* const* d_in, const int* in_sizes, int n_in,
                              void* d_out, int out_size)
{
    const float* qkv1 = (const float*)d_in[0];
    const float* qkv2 = (const float*)d_in[1];
    float* out = (float*)d_out;

    cudaFuncSetAttribute(inv_attn_mma2,
                         cudaFuncAttributeMaxDynamicSharedMemorySize, SMEM_TOTAL);
    inv_attn_mma2<<<dim3(512, 6, 1), 128, SMEM_TOTAL>>>(qkv1, qkv2, out);
}

// round 8
// speedup vs baseline: 1.0616x; 1.0616x over previous
#include <cuda_runtime.h>
#include <cuda_bf16.h>
#include <cstdint>

// Inverted window cross-attention via warp-level bf16 mma.sync.
// R8 = R6 structure (4 warps per window, 4 CTAs/SM) + fully-coalesced LDG
// (8 lanes x 16B per 128B token line) + split hi/lo tiles, pitch 80B
// (conflict-free ldsm + STS.64).

typedef unsigned long long ull;

constexpr int Bc = 4, Hc = 128, Wc = 128, Cc = 192;
constexpr int Lc = Hc * Wc;
constexpr long long BLC = (long long)Bc * Lc * Cc;

constexpr int TP  = 80;         // tile pitch bytes: banks/row = 20 -> 8-row conflict-free
constexpr int TSZ = 64 * TP;    // 5120 B per tile (64 rows x 32 bf16 used)
constexpr int SQ2H = 0*TSZ, SQ2L = 1*TSZ, SK2H = 2*TSZ, SK2L = 3*TSZ,
              SK1H = 4*TSZ, SK1L = 5*TSZ, SQ1H = 6*TSZ, SQ1L = 7*TSZ,
              SVH  = 8*TSZ, SVL  = 9*TSZ;
constexpr int SMEM_TOTAL = 10 * TSZ;   // 51200

__device__ __forceinline__ uint32_t smem_u32(const void* p) {
    uint32_t a;
    asm("{ .reg .u64 t; cvta.to.shared.u64 t, %1; cvt.u32.u64 %0, t; }" : "=r"(a) : "l"(p));
    return a;
}
__device__ __forceinline__ uint32_t pack_bf16(float lo, float hi) {
    uint32_t r; asm("cvt.rn.bf16x2.f32 %0, %1, %2;" : "=r"(r) : "f"(hi), "f"(lo)); return r;
}
__device__ __forceinline__ float bf_lo(uint32_t p) { return __uint_as_float(p << 16); }
__device__ __forceinline__ float bf_hi(uint32_t p) { return __uint_as_float(p & 0xffff0000u); }

__device__ __forceinline__ void split4(float4 x, uint2& h, uint2& l) {
    uint32_t h0 = pack_bf16(x.x, x.y), h1 = pack_bf16(x.z, x.w);
    h = make_uint2(h0, h1);
    l = make_uint2(pack_bf16(x.x - bf_lo(h0), x.y - bf_hi(h0)),
                   pack_bf16(x.z - bf_lo(h1), x.w - bf_hi(h1)));
}

__device__ __forceinline__ void ldsm4(uint32_t* r, uint32_t a) {
    asm volatile("ldmatrix.sync.aligned.m8n8.x4.shared.b16 {%0,%1,%2,%3}, [%4];"
                 : "=r"(r[0]), "=r"(r[1]), "=r"(r[2]), "=r"(r[3]) : "r"(a));
}
__device__ __forceinline__ void ldsm4t(uint32_t* r, uint32_t a) {
    asm volatile("ldmatrix.sync.aligned.m8n8.x4.trans.shared.b16 {%0,%1,%2,%3}, [%4];"
                 : "=r"(r[0]), "=r"(r[1]), "=r"(r[2]), "=r"(r[3]) : "r"(a));
}
__device__ __forceinline__ void mma16816(float* d, const uint32_t* a, const uint32_t* b) {
    asm volatile("mma.sync.aligned.m16n8k16.row.col.f32.bf16.bf16.f32 "
                 "{%0,%1,%2,%3}, {%4,%5,%6,%7}, {%8,%9}, {%0,%1,%2,%3};"
                 : "+f"(d[0]), "+f"(d[1]), "+f"(d[2]), "+f"(d[3])
                 : "r"(a[0]), "r"(a[1]), "r"(a[2]), "r"(a[3]), "r"(b[0]), "r"(b[1]));
}

__global__ __launch_bounds__(128, 4)
void inv_attn_mma3(const float* __restrict__ qkv1,
                   const float* __restrict__ qkv2,
                   float* __restrict__ out)
{
    extern __shared__ char sm[];
    const int tid  = threadIdx.x;
    const int lane = tid & 31, wid = tid >> 5;

    const int win = blockIdx.x, head = blockIdx.y;
    const int b = win >> 8, hb = (win >> 4) & 15, wb = win & 15;
    const int row0  = hb * 8 * Wc + wb * 8;
    const int cbase = head * 32;

    // -------- loader: coalesced (8 lanes x 16B cover each 128B token line) --------
    {
        const int ls = lane >> 3;          // token within 4-token group
        const int d4 = (lane & 7) * 4;     // float col (16B chunk)
        const int t0w = wid * 16;          // this warp's 16 tokens
#pragma unroll
        for (int g = 0; g < 4; g++) {
            const int t = t0w + 4 * g + ls;
            const long long gt =
                ((long long)b * Lc + row0 + (t >> 3) * Wc + (t & 7)) * Cc + cbase + d4;
            const int rb = t * TP + d4 * 2;   // hi-chunk byte offset in tile
            float4 x; uint2 h, l;
            x = *(const float4*)(qkv2 + gt);            // q2
            split4(x, h, l);
            *(uint2*)(sm + SQ2H + rb) = h;  *(uint2*)(sm + SQ2L + rb) = l;
            x = *(const float4*)(qkv2 + BLC + gt);      // k2
            split4(x, h, l);
            *(uint2*)(sm + SK2H + rb) = h;  *(uint2*)(sm + SK2L + rb) = l;
            x = *(const float4*)(qkv1 + BLC + gt);      // k1
            split4(x, h, l);
            *(uint2*)(sm + SK1H + rb) = h;  *(uint2*)(sm + SK1L + rb) = l;
            x = *(const float4*)(qkv1 + gt);            // q1
            split4(x, h, l);
            *(uint2*)(sm + SQ1H + rb) = h;  *(uint2*)(sm + SQ1L + rb) = l;
            float4 p = *(const float4*)(qkv1 + 2 * BLC + gt);   // v1+v2
            float4 q = *(const float4*)(qkv1 + 3 * BLC + gt);
            p.x += q.x; p.y += q.y; p.z += q.z; p.w += q.w;
            split4(p, h, l);
            *(uint2*)(sm + SVH + rb) = h;   *(uint2*)(sm + SVL + rb) = l;
        }
    }
    __syncthreads();

    const uint32_t smb = smem_u32(sm);
    const int mat = lane >> 3, li = lane & 7;
    const int r0 = wid * 16;               // this warp's 16 score rows

    // -------- A fragments (resident): q2/k2 hi+lo, kc in {0,1} --------
    const uint32_t aBase =
        (uint32_t)((r0 + li + ((mat & 1) << 3)) * TP + ((mat >> 1) << 4));
    uint32_t aQh[2][4], aQl[2][4], aKh[2][4], aKl[2][4];
#pragma unroll
    for (int kc = 0; kc < 2; kc++) {
        ldsm4(aQh[kc], smb + SQ2H + aBase + 32 * kc);
        ldsm4(aQl[kc], smb + SQ2L + aBase + 32 * kc);
        ldsm4(aKh[kc], smb + SK2H + aBase + 32 * kc);
        ldsm4(aKl[kc], smb + SK2L + aBase + 32 * kc);
    }

    // -------- score MMAs: 16 rows x 64 cols, 3-term bf16 split --------
    // B x4 covers two j-tiles: m0,m1 = j even (k cols 0-7 / 8-15), m2,m3 = j odd
    const uint32_t bBase =
        (uint32_t)((li + ((mat >> 1) << 3)) * TP + ((mat & 1) << 4));
    float sacc[8][4] = {};
#pragma unroll
    for (int jp = 0; jp < 4; jp++) {
#pragma unroll
        for (int kc = 0; kc < 2; kc++) {
            const uint32_t off = (uint32_t)(jp * 16 * TP + 32 * kc);
            uint32_t bkh[4], bkl[4], bqh[4], bql[4];
            ldsm4(bkh, smb + SK1H + bBase + off);
            ldsm4(bkl, smb + SK1L + bBase + off);
            ldsm4(bqh, smb + SQ1H + bBase + off);
            ldsm4(bql, smb + SQ1L + bBase + off);
#pragma unroll
            for (int jj = 0; jj < 2; jj++) {
                float* d = sacc[2 * jp + jj];
                mma16816(d, aQh[kc], bkh + 2 * jj);
                mma16816(d, aQl[kc], bkh + 2 * jj);
                mma16816(d, aQh[kc], bkl + 2 * jj);
                mma16816(d, aKh[kc], bqh + 2 * jj);
                mma16816(d, aKl[kc], bqh + 2 * jj);
                mma16816(d, aKh[kc], bql + 2 * jj);
            }
        }
    }

    // -------- register softmax --------
    const float scale = 0.17677669529663687f;  // 32^-0.5
    float s0 = 0.f, s1 = 0.f;
#pragma unroll
    for (int j = 0; j < 8; j++) {
        sacc[j][0] = __expf(2.f - scale * sacc[j][0]);
        sacc[j][1] = __expf(2.f - scale * sacc[j][1]);
        sacc[j][2] = __expf(2.f - scale * sacc[j][2]);
        sacc[j][3] = __expf(2.f - scale * sacc[j][3]);
        s0 += sacc[j][0] + sacc[j][1];
        s1 += sacc[j][2] + sacc[j][3];
    }
    s0 += __shfl_xor_sync(0xffffffffu, s0, 1);
    s0 += __shfl_xor_sync(0xffffffffu, s0, 2);
    s1 += __shfl_xor_sync(0xffffffffu, s1, 1);
    s1 += __shfl_xor_sync(0xffffffffu, s1, 2);
    const float inv0 = 1.0f / s0, inv1 = 1.0f / s1;

    // -------- D-frag -> A-frag repack with bf16 split --------
    uint32_t ehi[4][4], elo[4][4];
#pragma unroll
    for (int kc = 0; kc < 4; kc++) {
        const float* t0 = sacc[2 * kc];
        const float* t1 = sacc[2 * kc + 1];
        uint32_t h;
        h = pack_bf16(t0[0], t0[1]); ehi[kc][0] = h;
        elo[kc][0] = pack_bf16(t0[0] - bf_lo(h), t0[1] - bf_hi(h));
        h = pack_bf16(t0[2], t0[3]); ehi[kc][1] = h;
        elo[kc][1] = pack_bf16(t0[2] - bf_lo(h), t0[3] - bf_hi(h));
        h = pack_bf16(t1[0], t1[1]); ehi[kc][2] = h;
        elo[kc][2] = pack_bf16(t1[0] - bf_lo(h), t1[1] - bf_hi(h));
        h = pack_bf16(t1[2], t1[3]); ehi[kc][3] = h;
        elo[kc][3] = pack_bf16(t1[2] - bf_lo(h), t1[3] - bf_hi(h));
    }

    // -------- PV MMAs: V x4 (trans) covers token groups 32*kcp..+31 --------
    float oacc[4][4] = {};
#pragma unroll
    for (int t = 0; t < 4; t++) {
#pragma unroll
        for (int kcp = 0; kcp < 2; kcp++) {
            const uint32_t vAddr = (uint32_t)(
                (32 * kcp + li + ((mat & 1) << 3) + ((mat >> 1) << 4)) * TP + 16 * t);
            uint32_t bvh[4], bvl[4];
            ldsm4t(bvh, smb + SVH + vAddr);
            ldsm4t(bvl, smb + SVL + vAddr);
#pragma unroll
            for (int kk = 0; kk < 2; kk++) {
                const int kc = 2 * kcp + kk;
                mma16816(oacc[t], ehi[kc], bvh + 2 * kk);
                mma16816(oacc[t], ehi[kc], bvl + 2 * kk);
                mma16816(oacc[t], elo[kc], bvh + 2 * kk);
            }
        }
    }

    // -------- output (1/sum folded) --------
    {
        const int r  = lane >> 2;
        const int cq = (lane & 3) * 2;
        const int nA = r0 + r, nB = nA + 8;
        const long long gA =
            ((long long)b * Lc + row0 + (nA >> 3) * Wc + (nA & 7)) * Cc + cbase;
        const long long gB =
            ((long long)b * Lc + row0 + (nB >> 3) * Wc + (nB & 7)) * Cc + cbase;
#pragma unroll
        for (int t = 0; t < 4; t++) {
            *(float2*)(out + gA + 8 * t + cq) =
                make_float2(oacc[t][0] * inv0, oacc[t][1] * inv0);
            *(float2*)(out + gB + 8 * t + cq) =
                make_float2(oacc[t][2] * inv1, oacc[t][3] * inv1);
        }
    }
}

extern "C" void kernel_launch(void* const* d_in, const int* in_sizes, int n_in,
                              void* d_out, int out_size)
{
    const float* qkv1 = (const float*)d_in[0];
    const float* qkv2 = (const float*)d_in[1];
    float* out = (float*)d_out;

    cudaFuncSetAttribute(inv_attn_mma3,
                         cudaFuncAttributeMaxDynamicSharedMemorySize, SMEM_TOTAL);
    inv_attn_mma3<<<dim3(1024, 6, 1), 128, SMEM_TOTAL>>>(qkv1, qkv2, out);
}

// round 9
// speedup vs baseline: 1.3004x; 1.2250x over previous
#include <cuda_runtime.h>
#include <cuda_bf16.h>
#include <cstdint>

// Inverted window cross-attention via warp-level bf16 mma.sync (sm_80+ ISA).
// R9 = R6 (measured best) + float4 STG via shfl pair-exchange + exp constant fold.
// One CTA per (window, head): 1024 x 6 CTAs, 128 thr, 4 warps per window.

typedef unsigned long long ull;

constexpr int Bc = 4, Hc = 128, Wc = 128, Cc = 192;
constexpr int Lc = Hc * Wc;
constexpr long long BLC = (long long)Bc * Lc * Cc;

constexpr int PITCH = 72;                 // bf16 per smem row (144B, ldsm conflict-free)
// tiles of 64 x 72 bf16 (cols 0-31 = hi, 32-63 = lo)
constexpr int SQ2 = 0, SK2 = 9216, SK1 = 18432, SQ1 = 27648, SV = 36864;
constexpr int SMEM_TOTAL = 46080;

__device__ __forceinline__ uint32_t smem_u32(const void* p) {
    uint32_t a;
    asm("{ .reg .u64 t; cvta.to.shared.u64 t, %1; cvt.u32.u64 %0, t; }" : "=r"(a) : "l"(p));
    return a;
}
__device__ __forceinline__ uint32_t pack_bf16(float lo, float hi) {
    uint32_t r; asm("cvt.rn.bf16x2.f32 %0, %1, %2;" : "=r"(r) : "f"(hi), "f"(lo)); return r;
}
__device__ __forceinline__ float bf_lo(uint32_t p) { return __uint_as_float(p << 16); }
__device__ __forceinline__ float bf_hi(uint32_t p) { return __uint_as_float(p & 0xffff0000u); }

__device__ __forceinline__ void split8(const float* x, uint4& h, uint4& l) {
    uint32_t h0 = pack_bf16(x[0], x[1]), h1 = pack_bf16(x[2], x[3]);
    uint32_t h2 = pack_bf16(x[4], x[5]), h3 = pack_bf16(x[6], x[7]);
    h = make_uint4(h0, h1, h2, h3);
    l = make_uint4(pack_bf16(x[0]-bf_lo(h0), x[1]-bf_hi(h0)),
                   pack_bf16(x[2]-bf_lo(h1), x[3]-bf_hi(h1)),
                   pack_bf16(x[4]-bf_lo(h2), x[5]-bf_hi(h2)),
                   pack_bf16(x[6]-bf_lo(h3), x[7]-bf_hi(h3)));
}

__device__ __forceinline__ void ldsm4(uint32_t* r, uint32_t a) {
    asm volatile("ldmatrix.sync.aligned.m8n8.x4.shared.b16 {%0,%1,%2,%3}, [%4];"
                 : "=r"(r[0]), "=r"(r[1]), "=r"(r[2]), "=r"(r[3]) : "r"(a));
}
__device__ __forceinline__ void ldsm4t(uint32_t* r, uint32_t a) {
    asm volatile("ldmatrix.sync.aligned.m8n8.x4.trans.shared.b16 {%0,%1,%2,%3}, [%4];"
                 : "=r"(r[0]), "=r"(r[1]), "=r"(r[2]), "=r"(r[3]) : "r"(a));
}
__device__ __forceinline__ void mma16816(float* d, const uint32_t* a, const uint32_t* b) {
    asm volatile("mma.sync.aligned.m16n8k16.row.col.f32.bf16.bf16.f32 "
                 "{%0,%1,%2,%3}, {%4,%5,%6,%7}, {%8,%9}, {%0,%1,%2,%3};"
                 : "+f"(d[0]), "+f"(d[1]), "+f"(d[2]), "+f"(d[3])
                 : "r"(a[0]), "r"(a[1]), "r"(a[2]), "r"(a[3]), "r"(b[0]), "r"(b[1]));
}

__global__ __launch_bounds__(128, 4)
void inv_attn_mma4(const float* __restrict__ qkv1,
                   const float* __restrict__ qkv2,
                   float* __restrict__ out)
{
    extern __shared__ char sm[];
    const int tid  = threadIdx.x;
    const int lane = tid & 31, wid = tid >> 5;

    const int win = blockIdx.x, head = blockIdx.y;
    const int b = win >> 8, hb = (win >> 4) & 15, wb = win & 15;
    const int row0  = hb * 8 * Wc + wb * 8;
    const int cbase = head * 32;

    // ---------------- loader (R6 verbatim): fp32 -> bf16 hi/lo split tiles ----------
    {
        const int t  = tid >> 1;            // token 0..63
        const int dh = (tid & 1) * 16;      // half of head_dim
        const long long gt = ((long long)b * Lc + row0 + (t >> 3) * Wc + (t & 7)) * Cc + cbase;
        const float* srcs[4] = { qkv2 + gt, qkv2 + BLC + gt, qkv1 + BLC + gt, qkv1 + gt };
        const int dsts[4] = { SQ2, SK2, SK1, SQ1 };
#pragma unroll
        for (int s = 0; s < 4; s++) {
            const float* g = srcs[s];
            char* dbase = sm + dsts[s] + t * (PITCH * 2);
#pragma unroll
            for (int j = 0; j < 2; j++) {
                const int d = dh + 8 * j;
                float x[8]; uint4 h, l;
                *(float4*)(x)     = *(const float4*)(g + d);
                *(float4*)(x + 4) = *(const float4*)(g + d + 4);
                split8(x, h, l);
                *(uint4*)(dbase + d * 2)        = h;
                *(uint4*)(dbase + (32 + d) * 2) = l;
            }
        }
        const float* v1g = qkv1 + 2 * BLC + gt;
        const float* v2g = qkv1 + 3 * BLC + gt;
        char* dv = sm + SV + t * (PITCH * 2);
#pragma unroll
        for (int j = 0; j < 2; j++) {
            const int d = dh + 8 * j;
            float x[8]; uint4 h, l;
            float4 p = *(const float4*)(v1g + d), q = *(const float4*)(v2g + d);
            x[0] = p.x + q.x; x[1] = p.y + q.y; x[2] = p.z + q.z; x[3] = p.w + q.w;
            p = *(const float4*)(v1g + d + 4); q = *(const float4*)(v2g + d + 4);
            x[4] = p.x + q.x; x[5] = p.y + q.y; x[6] = p.z + q.z; x[7] = p.w + q.w;
            split8(x, h, l);
            *(uint4*)(dv + d * 2)        = h;
            *(uint4*)(dv + (32 + d) * 2) = l;
        }
    }
    __syncthreads();

    const uint32_t smb = smem_u32(sm);
    const int mat = lane >> 3, li = lane & 7;
    const int r0 = wid * 16;

    // ldmatrix lane-address parts (R6 verbatim)
    const uint32_t aPart = ((r0 + li + ((mat & 1) << 3)) * PITCH + ((mat >> 1) << 3)) * 2;
    const uint32_t bPart = (li * PITCH + ((mat & 1) << 3) + ((mat >> 1) << 5)) * 2;
    const uint32_t vPart = ((li + ((mat & 1) << 3)) * PITCH + ((mat >> 1) << 5)) * 2;

    // ---------------- score MMAs (R6 verbatim) ----------------
    uint32_t aQh[2][4], aQl[2][4], aKh[2][4], aKl[2][4];
#pragma unroll
    for (int kc = 0; kc < 2; kc++) {
        ldsm4(aQh[kc], smb + SQ2 + aPart + (16 * kc) * 2);
        ldsm4(aQl[kc], smb + SQ2 + aPart + (32 + 16 * kc) * 2);
        ldsm4(aKh[kc], smb + SK2 + aPart + (16 * kc) * 2);
        ldsm4(aKl[kc], smb + SK2 + aPart + (32 + 16 * kc) * 2);
    }
    float sacc[8][4] = {};
#pragma unroll
    for (int j = 0; j < 8; j++) {
#pragma unroll
        for (int kc = 0; kc < 2; kc++) {
            uint32_t bk[4], bq[4];
            const uint32_t off = (j * 8 * PITCH + 16 * kc) * 2;
            ldsm4(bk, smb + SK1 + bPart + off);     // {k1h, k1l}
            ldsm4(bq, smb + SQ1 + bPart + off);     // {q1h, q1l}
            mma16816(sacc[j], aQh[kc], bk);
            mma16816(sacc[j], aQl[kc], bk);
            mma16816(sacc[j], aQh[kc], bk + 2);
            mma16816(sacc[j], aKh[kc], bq);
            mma16816(sacc[j], aKl[kc], bq);
            mma16816(sacc[j], aKh[kc], bq + 2);
        }
    }

    // ---------------- register softmax (constant 2.0 folded out) ----------------
    const float scale = 0.17677669529663687f;  // 32^-0.5
    float s0 = 0.f, s1 = 0.f;
#pragma unroll
    for (int j = 0; j < 8; j++) {
        sacc[j][0] = __expf(-scale * sacc[j][0]);
        sacc[j][1] = __expf(-scale * sacc[j][1]);
        sacc[j][2] = __expf(-scale * sacc[j][2]);
        sacc[j][3] = __expf(-scale * sacc[j][3]);
        s0 += sacc[j][0] + sacc[j][1];
        s1 += sacc[j][2] + sacc[j][3];
    }
    s0 += __shfl_xor_sync(0xffffffffu, s0, 1);
    s0 += __shfl_xor_sync(0xffffffffu, s0, 2);
    s1 += __shfl_xor_sync(0xffffffffu, s1, 1);
    s1 += __shfl_xor_sync(0xffffffffu, s1, 2);
    const float inv0 = 1.0f / s0, inv1 = 1.0f / s1;

    // ---------------- D-frag -> A-frag repack with bf16 split (R6 verbatim) --------
    uint32_t ehi[4][4], elo[4][4];
#pragma unroll
    for (int kc = 0; kc < 4; kc++) {
        const float* t0 = sacc[2 * kc];
        const float* t1 = sacc[2 * kc + 1];
        uint32_t h;
        h = pack_bf16(t0[0], t0[1]); ehi[kc][0] = h;
        elo[kc][0] = pack_bf16(t0[0] - bf_lo(h), t0[1] - bf_hi(h));
        h = pack_bf16(t0[2], t0[3]); ehi[kc][1] = h;
        elo[kc][1] = pack_bf16(t0[2] - bf_lo(h), t0[3] - bf_hi(h));
        h = pack_bf16(t1[0], t1[1]); ehi[kc][2] = h;
        elo[kc][2] = pack_bf16(t1[0] - bf_lo(h), t1[1] - bf_hi(h));
        h = pack_bf16(t1[2], t1[3]); ehi[kc][3] = h;
        elo[kc][3] = pack_bf16(t1[2] - bf_lo(h), t1[3] - bf_hi(h));
    }

    // ---------------- PV MMAs (R6 verbatim) ----------------
    float oacc[4][4] = {};
#pragma unroll
    for (int t = 0; t < 4; t++) {
#pragma unroll
        for (int kc = 0; kc < 4; kc++) {
            uint32_t bv[4];
            ldsm4t(bv, smb + SV + vPart + (16 * kc * PITCH + 8 * t) * 2);  // {vh, vl}
            mma16816(oacc[t], ehi[kc], bv);
            mma16816(oacc[t], ehi[kc], bv + 2);
            mma16816(oacc[t], elo[kc], bv);
        }
    }

    // ---------------- output: shfl pair-exchange -> float4 stores ----------------
    {
        const int r  = lane >> 2;
        const int q  = lane & 3;
        const bool evn  = (q & 1) == 0;
        const int colb  = 4 * (q >> 1);          // 0 or 4
        const int n = r0 + r + (evn ? 0 : 8);    // even lanes: row nA, odd: row nB
        const long long g =
            ((long long)b * Lc + row0 + (n >> 3) * Wc + (n & 7)) * Cc + cbase + colb;
#pragma unroll
        for (int t = 0; t < 4; t++) {
            const float m0 = oacc[t][0] * inv0, m1 = oacc[t][1] * inv0;
            const float m2 = oacc[t][2] * inv1, m3 = oacc[t][3] * inv1;
            // even lane sends its nB values, receives partner's nA values (and vice versa)
            const float pa = __shfl_xor_sync(0xffffffffu, evn ? m2 : m0, 1);
            const float pb = __shfl_xor_sync(0xffffffffu, evn ? m3 : m1, 1);
            const float4 o4 = evn ? make_float4(m0, m1, pa, pb)
                                  : make_float4(pa, pb, m2, m3);
            *(float4*)(out + g + 8 * t) = o4;
        }
    }
}

extern "C" void kernel_launch(void* const* d_in, const int* in_sizes, int n_in,
                              void* d_out, int out_size)
{
    const float* qkv1 = (const float*)d_in[0];
    const float* qkv2 = (const float*)d_in[1];
    float* out = (float*)d_out;

    cudaFuncSetAttribute(inv_attn_mma4,
                         cudaFuncAttributeMaxDynamicSharedMemorySize, SMEM_TOTAL);
    inv_attn_mma4<<<dim3(1024, 6, 1), 128, SMEM_TOTAL>>>(qkv1, qkv2, out);
}

// round 10
// speedup vs baseline: 1.4610x; 1.1234x over previous
#include <cuda_runtime.h>
#include <cuda_bf16.h>
#include <cstdint>

// Inverted window cross-attention via warp-level bf16 mma.sync (sm_80+ ISA).
// R10 = R9 with ONE change: half-coalesced loader (8 tokens/LDG, 32B per lane),
// same PITCH-72 tiles, same STS.128, same MMA/softmax/output as R9/R6.

typedef unsigned long long ull;

constexpr int Bc = 4, Hc = 128, Wc = 128, Cc = 192;
constexpr int Lc = Hc * Wc;
constexpr long long BLC = (long long)Bc * Lc * Cc;

constexpr int PITCH = 72;                 // bf16 per smem row (144B)
constexpr int SQ2 = 0, SK2 = 9216, SK1 = 18432, SQ1 = 27648, SV = 36864;
constexpr int SMEM_TOTAL = 46080;

__device__ __forceinline__ uint32_t smem_u32(const void* p) {
    uint32_t a;
    asm("{ .reg .u64 t; cvta.to.shared.u64 t, %1; cvt.u32.u64 %0, t; }" : "=r"(a) : "l"(p));
    return a;
}
__device__ __forceinline__ uint32_t pack_bf16(float lo, float hi) {
    uint32_t r; asm("cvt.rn.bf16x2.f32 %0, %1, %2;" : "=r"(r) : "f"(hi), "f"(lo)); return r;
}
__device__ __forceinline__ float bf_lo(uint32_t p) { return __uint_as_float(p << 16); }
__device__ __forceinline__ float bf_hi(uint32_t p) { return __uint_as_float(p & 0xffff0000u); }

__device__ __forceinline__ void split8(const float* x, uint4& h, uint4& l) {
    uint32_t h0 = pack_bf16(x[0], x[1]), h1 = pack_bf16(x[2], x[3]);
    uint32_t h2 = pack_bf16(x[4], x[5]), h3 = pack_bf16(x[6], x[7]);
    h = make_uint4(h0, h1, h2, h3);
    l = make_uint4(pack_bf16(x[0]-bf_lo(h0), x[1]-bf_hi(h0)),
                   pack_bf16(x[2]-bf_lo(h1), x[3]-bf_hi(h1)),
                   pack_bf16(x[4]-bf_lo(h2), x[5]-bf_hi(h2)),
                   pack_bf16(x[6]-bf_lo(h3), x[7]-bf_hi(h3)));
}

__device__ __forceinline__ void ldsm4(uint32_t* r, uint32_t a) {
    asm volatile("ldmatrix.sync.aligned.m8n8.x4.shared.b16 {%0,%1,%2,%3}, [%4];"
                 : "=r"(r[0]), "=r"(r[1]), "=r"(r[2]), "=r"(r[3]) : "r"(a));
}
__device__ __forceinline__ void ldsm4t(uint32_t* r, uint32_t a) {
    asm volatile("ldmatrix.sync.aligned.m8n8.x4.trans.shared.b16 {%0,%1,%2,%3}, [%4];"
                 : "=r"(r[0]), "=r"(r[1]), "=r"(r[2]), "=r"(r[3]) : "r"(a));
}
__device__ __forceinline__ void mma16816(float* d, const uint32_t* a, const uint32_t* b) {
    asm volatile("mma.sync.aligned.m16n8k16.row.col.f32.bf16.bf16.f32 "
                 "{%0,%1,%2,%3}, {%4,%5,%6,%7}, {%8,%9}, {%0,%1,%2,%3};"
                 : "+f"(d[0]), "+f"(d[1]), "+f"(d[2]), "+f"(d[3])
                 : "r"(a[0]), "r"(a[1]), "r"(a[2]), "r"(a[3]), "r"(b[0]), "r"(b[1]));
}

__global__ __launch_bounds__(128, 4)
void inv_attn_mma5(const float* __restrict__ qkv1,
                   const float* __restrict__ qkv2,
                   float* __restrict__ out)
{
    extern __shared__ char sm[];
    const int tid  = threadIdx.x;
    const int lane = tid & 31, wid = tid >> 5;

    const int win = blockIdx.x, head = blockIdx.y;
    const int b = win >> 8, hb = (win >> 4) & 15, wb = win & 15;
    const int row0  = hb * 8 * Wc + wb * 8;
    const int cbase = head * 32;

    // ------- loader (R10): half-coalesced. lane -> token 16w+8g+(l>>2), 32B slice ----
    {
        const int d0 = (lane & 3) * 8;      // 8-float slice start
#pragma unroll
        for (int g = 0; g < 2; g++) {
            const int t = wid * 16 + g * 8 + (lane >> 2);
            const long long gt =
                ((long long)b * Lc + row0 + (t >> 3) * Wc + (t & 7)) * Cc + cbase + d0;
            const int rb = t * (PITCH * 2) + d0 * 2;    // hi bytes; lo at rb+64
            float x[8]; uint4 h, l4;
            // q2
            *(float4*)(x)     = *(const float4*)(qkv2 + gt);
            *(float4*)(x + 4) = *(const float4*)(qkv2 + gt + 4);
            split8(x, h, l4);
            *(uint4*)(sm + SQ2 + rb) = h;  *(uint4*)(sm + SQ2 + rb + 64) = l4;
            // k2
            *(float4*)(x)     = *(const float4*)(qkv2 + BLC + gt);
            *(float4*)(x + 4) = *(const float4*)(qkv2 + BLC + gt + 4);
            split8(x, h, l4);
            *(uint4*)(sm + SK2 + rb) = h;  *(uint4*)(sm + SK2 + rb + 64) = l4;
            // k1
            *(float4*)(x)     = *(const float4*)(qkv1 + BLC + gt);
            *(float4*)(x + 4) = *(const float4*)(qkv1 + BLC + gt + 4);
            split8(x, h, l4);
            *(uint4*)(sm + SK1 + rb) = h;  *(uint4*)(sm + SK1 + rb + 64) = l4;
            // q1
            *(float4*)(x)     = *(const float4*)(qkv1 + gt);
            *(float4*)(x + 4) = *(const float4*)(qkv1 + gt + 4);
            split8(x, h, l4);
            *(uint4*)(sm + SQ1 + rb) = h;  *(uint4*)(sm + SQ1 + rb + 64) = l4;
            // v1 + v2
            float4 p = *(const float4*)(qkv1 + 2 * BLC + gt);
            float4 q = *(const float4*)(qkv1 + 3 * BLC + gt);
            x[0] = p.x + q.x; x[1] = p.y + q.y; x[2] = p.z + q.z; x[3] = p.w + q.w;
            p = *(const float4*)(qkv1 + 2 * BLC + gt + 4);
            q = *(const float4*)(qkv1 + 3 * BLC + gt + 4);
            x[4] = p.x + q.x; x[5] = p.y + q.y; x[6] = p.z + q.z; x[7] = p.w + q.w;
            split8(x, h, l4);
            *(uint4*)(sm + SV + rb) = h;   *(uint4*)(sm + SV + rb + 64) = l4;
        }
    }
    __syncthreads();

    const uint32_t smb = smem_u32(sm);
    const int mat = lane >> 3, li = lane & 7;
    const int r0 = wid * 16;

    // ldmatrix lane-address parts (R6 verbatim)
    const uint32_t aPart = ((r0 + li + ((mat & 1) << 3)) * PITCH + ((mat >> 1) << 3)) * 2;
    const uint32_t bPart = (li * PITCH + ((mat & 1) << 3) + ((mat >> 1) << 5)) * 2;
    const uint32_t vPart = ((li + ((mat & 1) << 3)) * PITCH + ((mat >> 1) << 5)) * 2;

    // ---------------- score MMAs (R6 verbatim) ----------------
    uint32_t aQh[2][4], aQl[2][4], aKh[2][4], aKl[2][4];
#pragma unroll
    for (int kc = 0; kc < 2; kc++) {
        ldsm4(aQh[kc], smb + SQ2 + aPart + (16 * kc) * 2);
        ldsm4(aQl[kc], smb + SQ2 + aPart + (32 + 16 * kc) * 2);
        ldsm4(aKh[kc], smb + SK2 + aPart + (16 * kc) * 2);
        ldsm4(aKl[kc], smb + SK2 + aPart + (32 + 16 * kc) * 2);
    }
    float sacc[8][4] = {};
#pragma unroll
    for (int j = 0; j < 8; j++) {
#pragma unroll
        for (int kc = 0; kc < 2; kc++) {
            uint32_t bk[4], bq[4];
            const uint32_t off = (j * 8 * PITCH + 16 * kc) * 2;
            ldsm4(bk, smb + SK1 + bPart + off);     // {k1h, k1l}
            ldsm4(bq, smb + SQ1 + bPart + off);     // {q1h, q1l}
            mma16816(sacc[j], aQh[kc], bk);
            mma16816(sacc[j], aQl[kc], bk);
            mma16816(sacc[j], aQh[kc], bk + 2);
            mma16816(sacc[j], aKh[kc], bq);
            mma16816(sacc[j], aKl[kc], bq);
            mma16816(sacc[j], aKh[kc], bq + 2);
        }
    }

    // ---------------- register softmax (constant folded) ----------------
    const float scale = 0.17677669529663687f;  // 32^-0.5
    float s0 = 0.f, s1 = 0.f;
#pragma unroll
    for (int j = 0; j < 8; j++) {
        sacc[j][0] = __expf(-scale * sacc[j][0]);
        sacc[j][1] = __expf(-scale * sacc[j][1]);
        sacc[j][2] = __expf(-scale * sacc[j][2]);
        sacc[j][3] = __expf(-scale * sacc[j][3]);
        s0 += sacc[j][0] + sacc[j][1];
        s1 += sacc[j][2] + sacc[j][3];
    }
    s0 += __shfl_xor_sync(0xffffffffu, s0, 1);
    s0 += __shfl_xor_sync(0xffffffffu, s0, 2);
    s1 += __shfl_xor_sync(0xffffffffu, s1, 1);
    s1 += __shfl_xor_sync(0xffffffffu, s1, 2);
    const float inv0 = 1.0f / s0, inv1 = 1.0f / s1;

    // ---------------- D-frag -> A-frag repack with bf16 split ----------------
    uint32_t ehi[4][4], elo[4][4];
#pragma unroll
    for (int kc = 0; kc < 4; kc++) {
        const float* t0 = sacc[2 * kc];
        const float* t1 = sacc[2 * kc + 1];
        uint32_t h;
        h = pack_bf16(t0[0], t0[1]); ehi[kc][0] = h;
        elo[kc][0] = pack_bf16(t0[0] - bf_lo(h), t0[1] - bf_hi(h));
        h = pack_bf16(t0[2], t0[3]); ehi[kc][1] = h;
        elo[kc][1] = pack_bf16(t0[2] - bf_lo(h), t0[3] - bf_hi(h));
        h = pack_bf16(t1[0], t1[1]); ehi[kc][2] = h;
        elo[kc][2] = pack_bf16(t1[0] - bf_lo(h), t1[1] - bf_hi(h));
        h = pack_bf16(t1[2], t1[3]); ehi[kc][3] = h;
        elo[kc][3] = pack_bf16(t1[2] - bf_lo(h), t1[3] - bf_hi(h));
    }

    // ---------------- PV MMAs (R6 verbatim) ----------------
    float oacc[4][4] = {};
#pragma unroll
    for (int t = 0; t < 4; t++) {
#pragma unroll
        for (int kc = 0; kc < 4; kc++) {
            uint32_t bv[4];
            ldsm4t(bv, smb + SV + vPart + (16 * kc * PITCH + 8 * t) * 2);  // {vh, vl}
            mma16816(oacc[t], ehi[kc], bv);
            mma16816(oacc[t], ehi[kc], bv + 2);
            mma16816(oacc[t], elo[kc], bv);
        }
    }

    // ---------------- output: shfl pair-exchange -> float4 stores (R9) -----------
    {
        const int r  = lane >> 2;
        const int q  = lane & 3;
        const bool evn  = (q & 1) == 0;
        const int colb  = 4 * (q >> 1);
        const int n = r0 + r + (evn ? 0 : 8);
        const long long g =
            ((long long)b * Lc + row0 + (n >> 3) * Wc + (n & 7)) * Cc + cbase + colb;
#pragma unroll
        for (int t = 0; t < 4; t++) {
            const float m0 = oacc[t][0] * inv0, m1 = oacc[t][1] * inv0;
            const float m2 = oacc[t][2] * inv1, m3 = oacc[t][3] * inv1;
            const float pa = __shfl_xor_sync(0xffffffffu, evn ? m2 : m0, 1);
            const float pb = __shfl_xor_sync(0xffffffffu, evn ? m3 : m1, 1);
            const float4 o4 = evn ? make_float4(m0, m1, pa, pb)
                                  : make_float4(pa, pb, m2, m3);
            *(float4*)(out + g + 8 * t) = o4;
        }
    }
}

extern "C" void kernel_launch(void* const* d_in, const int* in_sizes, int n_in,
                              void* d_out, int out_size)
{
    const float* qkv1 = (const float*)d_in[0];
    const float* qkv2 = (const float*)d_in[1];
    float* out = (float*)d_out;

    cudaFuncSetAttribute(inv_attn_mma5,
                         cudaFuncAttributeMaxDynamicSharedMemorySize, SMEM_TOTAL);
    inv_attn_mma5<<<dim3(1024, 6, 1), 128, SMEM_TOTAL>>>(qkv1, qkv2, out);
}

// round 11
// speedup vs baseline: 1.5818x; 1.0827x over previous
#include <cuda_runtime.h>
#include <cuda_bf16.h>
#include <cstdint>

// Inverted window cross-attention via warp-level bf16 mma.sync (sm_80+ ISA).
// R11 = R10 + ONE change: chunk-permutation smem swizzle P=(c8+f(t&7))&7,
// f=[0,3,1,4,1,4,0,3], making STS.128 AND all ldmatrix accesses conflict-free.

typedef unsigned long long ull;

constexpr int Bc = 4, Hc = 128, Wc = 128, Cc = 192;
constexpr int Lc = Hc * Wc;
constexpr long long BLC = (long long)Bc * Lc * Cc;

constexpr int ROWB = 144;                 // bytes per row (8 data chunks + 16B pad)
constexpr int SQ2 = 0, SK2 = 9216, SK1 = 18432, SQ1 = 27648, SV = 36864;
constexpr int SMEM_TOTAL = 46080;

__device__ __forceinline__ uint32_t smem_u32(const void* p) {
    uint32_t a;
    asm("{ .reg .u64 t; cvta.to.shared.u64 t, %1; cvt.u32.u64 %0, t; }" : "=r"(a) : "l"(p));
    return a;
}
// chunk swizzle: f(t&7) = [0,3,1,4,1,4,0,3]
__device__ __forceinline__ int swz(int t) {
    return 3 * (t & 1) + (((t >> 1) ^ (t >> 2)) & 1);
}
__device__ __forceinline__ uint32_t pack_bf16(float lo, float hi) {
    uint32_t r; asm("cvt.rn.bf16x2.f32 %0, %1, %2;" : "=r"(r) : "f"(hi), "f"(lo)); return r;
}
__device__ __forceinline__ float bf_lo(uint32_t p) { return __uint_as_float(p << 16); }
__device__ __forceinline__ float bf_hi(uint32_t p) { return __uint_as_float(p & 0xffff0000u); }

__device__ __forceinline__ void split8(const float* x, uint4& h, uint4& l) {
    uint32_t h0 = pack_bf16(x[0], x[1]), h1 = pack_bf16(x[2], x[3]);
    uint32_t h2 = pack_bf16(x[4], x[5]), h3 = pack_bf16(x[6], x[7]);
    h = make_uint4(h0, h1, h2, h3);
    l = make_uint4(pack_bf16(x[0]-bf_lo(h0), x[1]-bf_hi(h0)),
                   pack_bf16(x[2]-bf_lo(h1), x[3]-bf_hi(h1)),
                   pack_bf16(x[4]-bf_lo(h2), x[5]-bf_hi(h2)),
                   pack_bf16(x[6]-bf_lo(h3), x[7]-bf_hi(h3)));
}

__device__ __forceinline__ void ldsm4(uint32_t* r, uint32_t a) {
    asm volatile("ldmatrix.sync.aligned.m8n8.x4.shared.b16 {%0,%1,%2,%3}, [%4];"
                 : "=r"(r[0]), "=r"(r[1]), "=r"(r[2]), "=r"(r[3]) : "r"(a));
}
__device__ __forceinline__ void ldsm4t(uint32_t* r, uint32_t a) {
    asm volatile("ldmatrix.sync.aligned.m8n8.x4.trans.shared.b16 {%0,%1,%2,%3}, [%4];"
                 : "=r"(r[0]), "=r"(r[1]), "=r"(r[2]), "=r"(r[3]) : "r"(a));
}
__device__ __forceinline__ void mma16816(float* d, const uint32_t* a, const uint32_t* b) {
    asm volatile("mma.sync.aligned.m16n8k16.row.col.f32.bf16.bf16.f32 "
                 "{%0,%1,%2,%3}, {%4,%5,%6,%7}, {%8,%9}, {%0,%1,%2,%3};"
                 : "+f"(d[0]), "+f"(d[1]), "+f"(d[2]), "+f"(d[3])
                 : "r"(a[0]), "r"(a[1]), "r"(a[2]), "r"(a[3]), "r"(b[0]), "r"(b[1]));
}

__global__ __launch_bounds__(128, 4)
void inv_attn_mma6(const float* __restrict__ qkv1,
                   const float* __restrict__ qkv2,
                   float* __restrict__ out)
{
    extern __shared__ char sm[];
    const int tid  = threadIdx.x;
    const int lane = tid & 31, wid = tid >> 5;

    const int win = blockIdx.x, head = blockIdx.y;
    const int b = win >> 8, hb = (win >> 4) & 15, wb = win & 15;
    const int row0  = hb * 8 * Wc + wb * 8;
    const int cbase = head * 32;

    // ------- loader (R10 pattern + swizzled STS offsets) -------
    {
        const int d0 = (lane & 3) * 8;                    // 8-float slice start
        const int ft = swz(lane >> 2);                    // token&7 = lane>>2
        const int hoff = (((lane & 3) + ft) & 7) * 16;    // hi chunk, swizzled
        const int loff = (((lane & 3) + 4 + ft) & 7) * 16;// lo chunk, swizzled
#pragma unroll
        for (int g = 0; g < 2; g++) {
            const int t = wid * 16 + g * 8 + (lane >> 2);
            const long long gt =
                ((long long)b * Lc + row0 + (t >> 3) * Wc + (t & 7)) * Cc + cbase + d0;
            const int rbh = t * ROWB + hoff;
            const int rbl = t * ROWB + loff;
            float x[8]; uint4 h, l4;
            // q2
            *(float4*)(x)     = *(const float4*)(qkv2 + gt);
            *(float4*)(x + 4) = *(const float4*)(qkv2 + gt + 4);
            split8(x, h, l4);
            *(uint4*)(sm + SQ2 + rbh) = h;  *(uint4*)(sm + SQ2 + rbl) = l4;
            // k2
            *(float4*)(x)     = *(const float4*)(qkv2 + BLC + gt);
            *(float4*)(x + 4) = *(const float4*)(qkv2 + BLC + gt + 4);
            split8(x, h, l4);
            *(uint4*)(sm + SK2 + rbh) = h;  *(uint4*)(sm + SK2 + rbl) = l4;
            // k1
            *(float4*)(x)     = *(const float4*)(qkv1 + BLC + gt);
            *(float4*)(x + 4) = *(const float4*)(qkv1 + BLC + gt + 4);
            split8(x, h, l4);
            *(uint4*)(sm + SK1 + rbh) = h;  *(uint4*)(sm + SK1 + rbl) = l4;
            // q1
            *(float4*)(x)     = *(const float4*)(qkv1 + gt);
            *(float4*)(x + 4) = *(const float4*)(qkv1 + gt + 4);
            split8(x, h, l4);
            *(uint4*)(sm + SQ1 + rbh) = h;  *(uint4*)(sm + SQ1 + rbl) = l4;
            // v1 + v2
            float4 p = *(const float4*)(qkv1 + 2 * BLC + gt);
            float4 q = *(const float4*)(qkv1 + 3 * BLC + gt);
            x[0] = p.x + q.x; x[1] = p.y + q.y; x[2] = p.z + q.z; x[3] = p.w + q.w;
            p = *(const float4*)(qkv1 + 2 * BLC + gt + 4);
            q = *(const float4*)(qkv1 + 3 * BLC + gt + 4);
            x[4] = p.x + q.x; x[5] = p.y + q.y; x[6] = p.z + q.z; x[7] = p.w + q.w;
            split8(x, h, l4);
            *(uint4*)(sm + SV + rbh) = h;   *(uint4*)(sm + SV + rbl) = l4;
        }
    }
    __syncthreads();

    const uint32_t smb = smem_u32(sm);
    const int mat = lane >> 3, li = lane & 7;
    const int r0 = wid * 16;
    const int fl = swz(li);                       // all ldsm rows satisfy row&7 == li

    // swizzled chunk offsets (bytes), hoisted per lane
    int aOffH[2], aOffL[2], bOff[2], vOff[4];
#pragma unroll
    for (int kc = 0; kc < 2; kc++) {
        aOffH[kc] = ((((mat >> 1) + 2 * kc) + fl) & 7) * 16;
        aOffL[kc] = ((((mat >> 1) + 2 * kc + 4) + fl) & 7) * 16;
        bOff[kc]  = ((((mat & 1) + 4 * (mat >> 1) + 2 * kc) + fl) & 7) * 16;
    }
#pragma unroll
    for (int t = 0; t < 4; t++)
        vOff[t] = (((4 * (mat >> 1) + t) + fl) & 7) * 16;

    const uint32_t aRow = (r0 + li + ((mat & 1) << 3)) * ROWB;
    const uint32_t bRow = li * ROWB;
    const uint32_t vRow = (li + ((mat & 1) << 3)) * ROWB;

    // ---------------- score MMAs ----------------
    uint32_t aQh[2][4], aQl[2][4], aKh[2][4], aKl[2][4];
#pragma unroll
    for (int kc = 0; kc < 2; kc++) {
        ldsm4(aQh[kc], smb + SQ2 + aRow + aOffH[kc]);
        ldsm4(aQl[kc], smb + SQ2 + aRow + aOffL[kc]);
        ldsm4(aKh[kc], smb + SK2 + aRow + aOffH[kc]);
        ldsm4(aKl[kc], smb + SK2 + aRow + aOffL[kc]);
    }
    float sacc[8][4] = {};
#pragma unroll
    for (int j = 0; j < 8; j++) {
#pragma unroll
        for (int kc = 0; kc < 2; kc++) {
            uint32_t bk[4], bq[4];
            const uint32_t off = bRow + j * 8 * ROWB + bOff[kc];
            ldsm4(bk, smb + SK1 + off);     // {k1h, k1l}
            ldsm4(bq, smb + SQ1 + off);     // {q1h, q1l}
            mma16816(sacc[j], aQh[kc], bk);
            mma16816(sacc[j], aQl[kc], bk);
            mma16816(sacc[j], aQh[kc], bk + 2);
            mma16816(sacc[j], aKh[kc], bq);
            mma16816(sacc[j], aKl[kc], bq);
            mma16816(sacc[j], aKh[kc], bq + 2);
        }
    }

    // ---------------- register softmax ----------------
    const float scale = 0.17677669529663687f;  // 32^-0.5
    float s0 = 0.f, s1 = 0.f;
#pragma unroll
    for (int j = 0; j < 8; j++) {
        sacc[j][0] = __expf(-scale * sacc[j][0]);
        sacc[j][1] = __expf(-scale * sacc[j][1]);
        sacc[j][2] = __expf(-scale * sacc[j][2]);
        sacc[j][3] = __expf(-scale * sacc[j][3]);
        s0 += sacc[j][0] + sacc[j][1];
        s1 += sacc[j][2] + sacc[j][3];
    }
    s0 += __shfl_xor_sync(0xffffffffu, s0, 1);
    s0 += __shfl_xor_sync(0xffffffffu, s0, 2);
    s1 += __shfl_xor_sync(0xffffffffu, s1, 1);
    s1 += __shfl_xor_sync(0xffffffffu, s1, 2);
    const float inv0 = 1.0f / s0, inv1 = 1.0f / s1;

    // ---------------- D-frag -> A-frag repack with bf16 split ----------------
    uint32_t ehi[4][4], elo[4][4];
#pragma unroll
    for (int kc = 0; kc < 4; kc++) {
        const float* t0 = sacc[2 * kc];
        const float* t1 = sacc[2 * kc + 1];
        uint32_t h;
        h = pack_bf16(t0[0], t0[1]); ehi[kc][0] = h;
        elo[kc][0] = pack_bf16(t0[0] - bf_lo(h), t0[1] - bf_hi(h));
        h = pack_bf16(t0[2], t0[3]); ehi[kc][1] = h;
        elo[kc][1] = pack_bf16(t0[2] - bf_lo(h), t0[3] - bf_hi(h));
        h = pack_bf16(t1[0], t1[1]); ehi[kc][2] = h;
        elo[kc][2] = pack_bf16(t1[0] - bf_lo(h), t1[1] - bf_hi(h));
        h = pack_bf16(t1[2], t1[3]); ehi[kc][3] = h;
        elo[kc][3] = pack_bf16(t1[2] - bf_lo(h), t1[3] - bf_hi(h));
    }

    // ---------------- PV MMAs ----------------
    float oacc[4][4] = {};
#pragma unroll
    for (int t = 0; t < 4; t++) {
#pragma unroll
        for (int kc = 0; kc < 4; kc++) {
            uint32_t bv[4];
            ldsm4t(bv, smb + SV + vRow + kc * 16 * ROWB + vOff[t]);  // {vh, vl}
            mma16816(oacc[t], ehi[kc], bv);
            mma16816(oacc[t], ehi[kc], bv + 2);
            mma16816(oacc[t], elo[kc], bv);
        }
    }

    // ---------------- output: shfl pair-exchange -> float4 stores ----------------
    {
        const int r  = lane >> 2;
        const int q  = lane & 3;
        const bool evn  = (q & 1) == 0;
        const int colb  = 4 * (q >> 1);
        const int n = r0 + r + (evn ? 0 : 8);
        const long long g =
            ((long long)b * Lc + row0 + (n >> 3) * Wc + (n & 7)) * Cc + cbase + colb;
#pragma unroll
        for (int t = 0; t < 4; t++) {
            const float m0 = oacc[t][0] * inv0, m1 = oacc[t][1] * inv0;
            const float m2 = oacc[t][2] * inv1, m3 = oacc[t][3] * inv1;
            const float pa = __shfl_xor_sync(0xffffffffu, evn ? m2 : m0, 1);
            const float pb = __shfl_xor_sync(0xffffffffu, evn ? m3 : m1, 1);
            const float4 o4 = evn ? make_float4(m0, m1, pa, pb)
                                  : make_float4(pa, pb, m2, m3);
            *(float4*)(out + g + 8 * t) = o4;
        }
    }
}

extern "C" void kernel_launch(void* const* d_in, const int* in_sizes, int n_in,
                              void* d_out, int out_size)
{
    const float* qkv1 = (const float*)d_in[0];
    const float* qkv2 = (const float*)d_in[1];
    float* out = (float*)d_out;

    cudaFuncSetAttribute(inv_attn_mma6,
                         cudaFuncAttributeMaxDynamicSharedMemorySize, SMEM_TOTAL);
    inv_attn_mma6<<<dim3(1024, 6, 1), 128, SMEM_TOTAL>>>(qkv1, qkv2, out);
}

// round 12
// speedup vs baseline: 1.5825x; 1.0005x over previous
#include <cuda_runtime.h>
#include <cuda_bf16.h>
#include <cstdint>

// Inverted window cross-attention via warp-level bf16 mma.sync (sm_80+ ISA).
// R12 = R11 + ONE change: fully-coalesced loader (8 lanes x 16B per token line,
// 4 lines fully used per LDG). Same swizzled tiles (P=(c+f(t&7))&7), same
// MMA/softmax/output as R11.

typedef unsigned long long ull;

constexpr int Bc = 4, Hc = 128, Wc = 128, Cc = 192;
constexpr int Lc = Hc * Wc;
constexpr long long BLC = (long long)Bc * Lc * Cc;

constexpr int ROWB = 144;                 // bytes per row (8 data chunks + 16B pad)
constexpr int SQ2 = 0, SK2 = 9216, SK1 = 18432, SQ1 = 27648, SV = 36864;
constexpr int SMEM_TOTAL = 46080;

__device__ __forceinline__ uint32_t smem_u32(const void* p) {
    uint32_t a;
    asm("{ .reg .u64 t; cvta.to.shared.u64 t, %1; cvt.u32.u64 %0, t; }" : "=r"(a) : "l"(p));
    return a;
}
// chunk swizzle: f(t&7) = [0,3,1,4,1,4,0,3]
__device__ __forceinline__ int swz(int t) {
    return 3 * (t & 1) + (((t >> 1) ^ (t >> 2)) & 1);
}
__device__ __forceinline__ uint32_t pack_bf16(float lo, float hi) {
    uint32_t r; asm("cvt.rn.bf16x2.f32 %0, %1, %2;" : "=r"(r) : "f"(hi), "f"(lo)); return r;
}
__device__ __forceinline__ float bf_lo(uint32_t p) { return __uint_as_float(p << 16); }
__device__ __forceinline__ float bf_hi(uint32_t p) { return __uint_as_float(p & 0xffff0000u); }

// split 4 floats -> hi uint2 + lo uint2 (bf16x2 each)
__device__ __forceinline__ void split4(float4 x, uint2& h, uint2& l) {
    uint32_t h0 = pack_bf16(x.x, x.y), h1 = pack_bf16(x.z, x.w);
    h = make_uint2(h0, h1);
    l = make_uint2(pack_bf16(x.x - bf_lo(h0), x.y - bf_hi(h0)),
                   pack_bf16(x.z - bf_lo(h1), x.w - bf_hi(h1)));
}

__device__ __forceinline__ void ldsm4(uint32_t* r, uint32_t a) {
    asm volatile("ldmatrix.sync.aligned.m8n8.x4.shared.b16 {%0,%1,%2,%3}, [%4];"
                 : "=r"(r[0]), "=r"(r[1]), "=r"(r[2]), "=r"(r[3]) : "r"(a));
}
__device__ __forceinline__ void ldsm4t(uint32_t* r, uint32_t a) {
    asm volatile("ldmatrix.sync.aligned.m8n8.x4.trans.shared.b16 {%0,%1,%2,%3}, [%4];"
                 : "=r"(r[0]), "=r"(r[1]), "=r"(r[2]), "=r"(r[3]) : "r"(a));
}
__device__ __forceinline__ void mma16816(float* d, const uint32_t* a, const uint32_t* b) {
    asm volatile("mma.sync.aligned.m16n8k16.row.col.f32.bf16.bf16.f32 "
                 "{%0,%1,%2,%3}, {%4,%5,%6,%7}, {%8,%9}, {%0,%1,%2,%3};"
                 : "+f"(d[0]), "+f"(d[1]), "+f"(d[2]), "+f"(d[3])
                 : "r"(a[0]), "r"(a[1]), "r"(a[2]), "r"(a[3]), "r"(b[0]), "r"(b[1]));
}

__global__ __launch_bounds__(128, 4)
void inv_attn_mma7(const float* __restrict__ qkv1,
                   const float* __restrict__ qkv2,
                   float* __restrict__ out)
{
    extern __shared__ char sm[];
    const int tid  = threadIdx.x;
    const int lane = tid & 31, wid = tid >> 5;

    const int win = blockIdx.x, head = blockIdx.y;
    const int b = win >> 8, hb = (win >> 4) & 15, wb = win & 15;
    const int row0  = hb * 8 * Wc + wb * 8;
    const int cbase = head * 32;

    // ------- loader (R12): fully coalesced, 8 lanes x 16B per 128B token line ------
    {
        const int tg   = lane >> 3;          // token within 4-group
        const int fc   = lane & 7;           // 16B float chunk 0..7
        const int bc   = fc >> 1;            // bf16 chunk 0..3
        const int half = (fc & 1) * 8;       // 8B half within bf16 chunk
#pragma unroll
        for (int g = 0; g < 4; g++) {
            const int t = wid * 16 + 4 * g + tg;
            const int ft = swz(t & 7);
            const int hoff = ((bc + ft) & 7) * 16 + half;
            const int loff = ((bc + 4 + ft) & 7) * 16 + half;
            const long long gt =
                ((long long)b * Lc + row0 + (t >> 3) * Wc + (t & 7)) * Cc + cbase + fc * 4;
            const int rb = t * ROWB;
            float4 x; uint2 h, l;
            // q2
            x = *(const float4*)(qkv2 + gt);
            split4(x, h, l);
            *(uint2*)(sm + SQ2 + rb + hoff) = h;  *(uint2*)(sm + SQ2 + rb + loff) = l;
            // k2
            x = *(const float4*)(qkv2 + BLC + gt);
            split4(x, h, l);
            *(uint2*)(sm + SK2 + rb + hoff) = h;  *(uint2*)(sm + SK2 + rb + loff) = l;
            // k1
            x = *(const float4*)(qkv1 + BLC + gt);
            split4(x, h, l);
            *(uint2*)(sm + SK1 + rb + hoff) = h;  *(uint2*)(sm + SK1 + rb + loff) = l;
            // q1
            x = *(const float4*)(qkv1 + gt);
            split4(x, h, l);
            *(uint2*)(sm + SQ1 + rb + hoff) = h;  *(uint2*)(sm + SQ1 + rb + loff) = l;
            // v1 + v2
            float4 p = *(const float4*)(qkv1 + 2 * BLC + gt);
            float4 q = *(const float4*)(qkv1 + 3 * BLC + gt);
            x = make_float4(p.x + q.x, p.y + q.y, p.z + q.z, p.w + q.w);
            split4(x, h, l);
            *(uint2*)(sm + SV + rb + hoff) = h;   *(uint2*)(sm + SV + rb + loff) = l;
        }
    }
    __syncthreads();

    const uint32_t smb = smem_u32(sm);
    const int mat = lane >> 3, li = lane & 7;
    const int r0 = wid * 16;
    const int fl = swz(li);                       // all ldsm rows satisfy row&7 == li

    // swizzled chunk offsets (bytes), hoisted per lane (R11 verbatim)
    int aOffH[2], aOffL[2], bOff[2], vOff[4];
#pragma unroll
    for (int kc = 0; kc < 2; kc++) {
        aOffH[kc] = ((((mat >> 1) + 2 * kc) + fl) & 7) * 16;
        aOffL[kc] = ((((mat >> 1) + 2 * kc + 4) + fl) & 7) * 16;
        bOff[kc]  = ((((mat & 1) + 4 * (mat >> 1) + 2 * kc) + fl) & 7) * 16;
    }
#pragma unroll
    for (int t = 0; t < 4; t++)
        vOff[t] = (((4 * (mat >> 1) + t) + fl) & 7) * 16;

    const uint32_t aRow = (r0 + li + ((mat & 1) << 3)) * ROWB;
    const uint32_t bRow = li * ROWB;
    const uint32_t vRow = (li + ((mat & 1) << 3)) * ROWB;

    // ---------------- score MMAs (R11 verbatim) ----------------
    uint32_t aQh[2][4], aQl[2][4], aKh[2][4], aKl[2][4];
#pragma unroll
    for (int kc = 0; kc < 2; kc++) {
        ldsm4(aQh[kc], smb + SQ2 + aRow + aOffH[kc]);
        ldsm4(aQl[kc], smb + SQ2 + aRow + aOffL[kc]);
        ldsm4(aKh[kc], smb + SK2 + aRow + aOffH[kc]);
        ldsm4(aKl[kc], smb + SK2 + aRow + aOffL[kc]);
    }
    float sacc[8][4] = {};
#pragma unroll
    for (int j = 0; j < 8; j++) {
#pragma unroll
        for (int kc = 0; kc < 2; kc++) {
            uint32_t bk[4], bq[4];
            const uint32_t off = bRow + j * 8 * ROWB + bOff[kc];
            ldsm4(bk, smb + SK1 + off);     // {k1h, k1l}
            ldsm4(bq, smb + SQ1 + off);     // {q1h, q1l}
            mma16816(sacc[j], aQh[kc], bk);
            mma16816(sacc[j], aQl[kc], bk);
            mma16816(sacc[j], aQh[kc], bk + 2);
            mma16816(sacc[j], aKh[kc], bq);
            mma16816(sacc[j], aKl[kc], bq);
            mma16816(sacc[j], aKh[kc], bq + 2);
        }
    }

    // ---------------- register softmax (R11 verbatim) ----------------
    const float scale = 0.17677669529663687f;  // 32^-0.5
    float s0 = 0.f, s1 = 0.f;
#pragma unroll
    for (int j = 0; j < 8; j++) {
        sacc[j][0] = __expf(-scale * sacc[j][0]);
        sacc[j][1] = __expf(-scale * sacc[j][1]);
        sacc[j][2] = __expf(-scale * sacc[j][2]);
        sacc[j][3] = __expf(-scale * sacc[j][3]);
        s0 += sacc[j][0] + sacc[j][1];
        s1 += sacc[j][2] + sacc[j][3];
    }
    s0 += __shfl_xor_sync(0xffffffffu, s0, 1);
    s0 += __shfl_xor_sync(0xffffffffu, s0, 2);
    s1 += __shfl_xor_sync(0xffffffffu, s1, 1);
    s1 += __shfl_xor_sync(0xffffffffu, s1, 2);
    const float inv0 = 1.0f / s0, inv1 = 1.0f / s1;

    // ---------------- D-frag -> A-frag repack with bf16 split ----------------
    uint32_t ehi[4][4], elo[4][4];
#pragma unroll
    for (int kc = 0; kc < 4; kc++) {
        const float* t0 = sacc[2 * kc];
        const float* t1 = sacc[2 * kc + 1];
        uint32_t h;
        h = pack_bf16(t0[0], t0[1]); ehi[kc][0] = h;
        elo[kc][0] = pack_bf16(t0[0] - bf_lo(h), t0[1] - bf_hi(h));
        h = pack_bf16(t0[2], t0[3]); ehi[kc][1] = h;
        elo[kc][1] = pack_bf16(t0[2] - bf_lo(h), t0[3] - bf_hi(h));
        h = pack_bf16(t1[0], t1[1]); ehi[kc][2] = h;
        elo[kc][2] = pack_bf16(t1[0] - bf_lo(h), t1[1] - bf_hi(h));
        h = pack_bf16(t1[2], t1[3]); ehi[kc][3] = h;
        elo[kc][3] = pack_bf16(t1[2] - bf_lo(h), t1[3] - bf_hi(h));
    }

    // ---------------- PV MMAs (R11 verbatim) ----------------
    float oacc[4][4] = {};
#pragma unroll
    for (int t = 0; t < 4; t++) {
#pragma unroll
        for (int kc = 0; kc < 4; kc++) {
            uint32_t bv[4];
            ldsm4t(bv, smb + SV + vRow + kc * 16 * ROWB + vOff[t]);  // {vh, vl}
            mma16816(oacc[t], ehi[kc], bv);
            mma16816(oacc[t], ehi[kc], bv + 2);
            mma16816(oacc[t], elo[kc], bv);
        }
    }

    // ---------------- output: shfl pair-exchange -> float4 stores ----------------
    {
        const int r  = lane >> 2;
        const int q  = lane & 3;
        const bool evn  = (q & 1) == 0;
        const int colb  = 4 * (q >> 1);
        const int n = r0 + r + (evn ? 0 : 8);
        const long long g =
            ((long long)b * Lc + row0 + (n >> 3) * Wc + (n & 7)) * Cc + cbase + colb;
#pragma unroll
        for (int t = 0; t < 4; t++) {
            const float m0 = oacc[t][0] * inv0, m1 = oacc[t][1] * inv0;
            const float m2 = oacc[t][2] * inv1, m3 = oacc[t][3] * inv1;
            const float pa = __shfl_xor_sync(0xffffffffu, evn ? m2 : m0, 1);
            const float pb = __shfl_xor_sync(0xffffffffu, evn ? m3 : m1, 1);
            const float4 o4 = evn ? make_float4(m0, m1, pa, pb)
                                  : make_float4(pa, pb, m2, m3);
            *(float4*)(out + g + 8 * t) = o4;
        }
    }
}

extern "C" void kernel_launch(void* const* d_in, const int* in_sizes, int n_in,
                              void* d_out, int out_size)
{
    const float* qkv1 = (const float*)d_in[0];
    const float* qkv2 = (const float*)d_in[1];
    float* out = (float*)d_out;

    cudaFuncSetAttribute(inv_attn_mma7,
                         cudaFuncAttributeMaxDynamicSharedMemorySize, SMEM_TOTAL);
    inv_attn_mma7<<<dim3(1024, 6, 1), 128, SMEM_TOTAL>>>(qkv1, qkv2, out);
}